// round 7
// baseline (speedup 1.0000x reference)
#include <cuda_runtime.h>

#define NN 10000
#define HID 16
#define LAB 7
#define KC 32             // k per chunk
#define RPB 64            // rows per block (8 warps x 8 rows)
#define KSPLIT 32
#define KPB 320           // k per block (10 chunks)
#define NCHB 10
#define FPITCH 40         // floats per staged feature row (banks: 8r+q distinct)
#define WPITCH 20         // floats per staged W row (banks: 20*row, Δrow=1 ok)

__device__ int g_is64;
__device__ __align__(16) float g_deg_src[NN];
__device__ __align__(16) float g_deg_dst[NN];
__device__ __align__(16) float g_norm_src[NN];
__device__ __align__(16) float g_norm_dst[NN];
__device__ __align__(16) float g_h[NN * HID];   // features @ W1 (unnormalized)
__device__ __align__(16) float g_agg1[NN * HID];
__device__ __align__(16) float g_h2[NN * 8];
__device__ __align__(16) float g_agg2[NN * 8];

// ---------- helpers ----------
__device__ __forceinline__ unsigned long long pack2(float x) {
    unsigned long long r;
    asm("mov.b64 %0, {%1, %1};" : "=l"(r) : "f"(x));
    return r;
}
__device__ __forceinline__ void fma2(unsigned long long& d, unsigned long long a,
                                     unsigned long long b) {
    asm("fma.rn.f32x2 %0, %1, %2, %0;" : "+l"(d) : "l"(a), "l"(b));
}
__device__ __forceinline__ unsigned long long add2(unsigned long long a,
                                                   unsigned long long b) {
    unsigned long long r;
    asm("add.rn.f32x2 %0, %1, %2;" : "=l"(r) : "l"(a), "l"(b));
    return r;
}
__device__ __forceinline__ float2 unpack2(unsigned long long v) {
    float2 u;
    asm("mov.b64 {%0, %1}, %2;" : "=f"(u.x), "=f"(u.y) : "l"(v));
    return u;
}
__device__ __forceinline__ void redg_v4(float* p, float4 v) {
    unsigned long long gp;
    asm("cvta.to.global.u64 %0, %1;" : "=l"(gp) : "l"(p));
    asm volatile("red.global.add.v4.f32 [%0], {%1, %2, %3, %4};"
                 ::"l"(gp), "f"(v.x), "f"(v.y), "f"(v.z), "f"(v.w) : "memory");
}
__device__ __forceinline__ void redg_f32(float* p, float v) {
    unsigned long long gp;
    asm("cvta.to.global.u64 %0, %1;" : "=l"(gp) : "l"(p));
    asm volatile("red.global.add.f32 [%0], %1;" ::"l"(gp), "f"(v) : "memory");
}
__device__ __forceinline__ void cp16(unsigned smem_dst, const void* gsrc, int sz) {
    asm volatile("cp.async.cg.shared.global [%0], [%1], 16, %2;"
                 ::"r"(smem_dst), "l"(gsrc), "r"(sz));
}
__device__ __forceinline__ int eidx(const void* p, int e, int is64) {
    int v = ((const int*)p)[is64 ? 2 * e : e];
    return min(max(v, 0), NN - 1);
}

// ---------- K0: detect dtype + zero scratch ----------
__global__ void k_init(const int* __restrict__ src) {
    int i = blockIdx.x * blockDim.x + threadIdx.x;
    if (i == 0) {
        int all_odd_zero = 1;
        for (int t = 1; t < 256; t += 2)
            if (src[t] != 0) { all_odd_zero = 0; break; }
        g_is64 = all_odd_zero;
    }
    int stride = gridDim.x * blockDim.x;
    for (int t = i; t < NN; t += stride) { g_deg_src[t] = 0.f; g_deg_dst[t] = 0.f; }
    for (int t = i; t < NN * HID; t += stride) { g_h[t] = 0.f; g_agg1[t] = 0.f; }
    for (int t = i; t < NN * 8; t += stride) g_agg2[t] = 0.f;
}

// ---------- K1: degrees ----------
__global__ void k_deg(const void* __restrict__ src, const void* __restrict__ dst, int nE) {
    int e = blockIdx.x * blockDim.x + threadIdx.x;
    if (e >= nE) return;
    int is64 = g_is64;
    redg_f32(&g_deg_src[eidx(src, e, is64)], 1.f);
    redg_f32(&g_deg_dst[eidx(dst, e, is64)], 1.f);
}

// ---------- K2: norms ----------
__global__ void k_norm() {
    int n = blockIdx.x * blockDim.x + threadIdx.x;
    if (n >= NN) return;
    g_norm_src[n] = rsqrtf(fmaxf(g_deg_src[n], 1.f));
    g_norm_dst[n] = rsqrtf(fmaxf(g_deg_dst[n], 1.f));
}

// ---------- K3: g_h += features @ W1 (per-warp pipelines, no block sync) ----------
// Block = 64 rows x 320 k. W slice staged once. Each warp: private 2-stage
// cp.async ring over its 8 rows. Lane (q = lane&7, r = lane>>3) computes rows
// {r, r+4} for k in {q, q+8, q+16, q+24} of each 32-k chunk:
//   8 LDS.32 feat + 16 LDS.128 W (both conflict-free) + 64 FFMA2.
// Epilogue: shfl-bfly over q bits, lanes q==0 RED partials to g_h.
__global__ void __launch_bounds__(256, 3)
k_gemm1(const float* __restrict__ feat, const float* __restrict__ W1) {
    __shared__ __align__(16) float sW[KPB * WPITCH];          // 25600 B
    __shared__ __align__(16) float sF[8][2][8 * FPITCH];      // 20480 B

    const int tid = threadIdx.x;
    const int w = tid >> 5;
    const int lane = tid & 31;
    const int q = lane & 7;
    const int r = lane >> 3;
    const int rowBase = blockIdx.x * RPB;
    const int k0 = blockIdx.y * KPB;

    // ---- stage W slice (group 0) ----
#pragma unroll
    for (int i = 0; i < 5; i++) {
        int u = tid + 256 * i;               // 1280 units: row*4 + quad
        int row = u >> 2, quad = u & 3;
        int gk = k0 + row;
        cp16((unsigned)__cvta_generic_to_shared(&sW[row * WPITCH + quad * 4]),
             W1 + (size_t)min(gk, NN - 1) * HID + quad * 4, (gk < NN) ? 16 : 0);
    }
    asm volatile("cp.async.commit_group;" ::: "memory");

    // ---- per-warp feature issue ----
    const int myRow = rowBase + w * 8;
    auto issue = [&](int c) {
        if (c < NCHB) {
            const int cb = c & 1;
            const int cc0 = k0 + c * KC;
#pragma unroll
            for (int i = 0; i < 2; i++) {
                int u = lane + 32 * i;        // 64 units: row*8 + quad
                int rl = u >> 3, qd = u & 7;
                int gr = myRow + rl, gc = cc0 + qd * 4;
                int ok = (gr < NN && gc < NN);
                cp16((unsigned)__cvta_generic_to_shared(&sF[w][cb][rl * FPITCH + qd * 4]),
                     feat + (size_t)min(gr, NN - 1) * NN + min(gc, NN - 4), ok ? 16 : 0);
            }
        }
        asm volatile("cp.async.commit_group;" ::: "memory");
    };

    issue(0);
    issue(1);
    asm volatile("cp.async.wait_group 2;" ::: "memory");   // W done (for my thread)
    __syncthreads();                                       // W done for all threads

    unsigned long long acc[16];
#pragma unroll
    for (int i = 0; i < 16; i++) acc[i] = 0ull;

    for (int c = 0; c < NCHB; c++) {
        asm volatile("cp.async.wait_group 1;" ::: "memory");  // chunk c landed
        __syncwarp();
        const float* fb = sF[w][c & 1];
#pragma unroll
        for (int kk = 0; kk < 4; kk++) {
            const int k = q + 8 * kk;
            float f0 = fb[r * FPITCH + k];
            float f1 = fb[(r + 4) * FPITCH + k];
            const ulonglong2* wr = (const ulonglong2*)(sW + (c * KC + k) * WPITCH);
            ulonglong2 q0 = wr[0], q1 = wr[1], q2 = wr[2], q3 = wr[3];
            unsigned long long p0 = pack2(f0);
            unsigned long long p1 = pack2(f1);
            fma2(acc[0], q0.x, p0); fma2(acc[1], q0.y, p0);
            fma2(acc[2], q1.x, p0); fma2(acc[3], q1.y, p0);
            fma2(acc[4], q2.x, p0); fma2(acc[5], q2.y, p0);
            fma2(acc[6], q3.x, p0); fma2(acc[7], q3.y, p0);
            fma2(acc[8], q0.x, p1); fma2(acc[9], q0.y, p1);
            fma2(acc[10], q1.x, p1); fma2(acc[11], q1.y, p1);
            fma2(acc[12], q2.x, p1); fma2(acc[13], q2.y, p1);
            fma2(acc[14], q3.x, p1); fma2(acc[15], q3.y, p1);
        }
        __syncwarp();
        issue(c + 2);
    }

    // ---- reduce over q (lane bits 0..2) ----
#pragma unroll
    for (int s = 1; s <= 4; s <<= 1) {
#pragma unroll
        for (int i = 0; i < 16; i++) {
            unsigned long long o = __shfl_xor_sync(0xffffffffu, acc[i], s);
            acc[i] = add2(acc[i], o);
        }
    }
    if (q == 0) {
        int gr0 = myRow + r;
        int gr1 = gr0 + 4;
        if (gr0 < NN) {
#pragma unroll
            for (int j = 0; j < 4; j++) {
                float2 u0 = unpack2(acc[2 * j]);
                float2 u1 = unpack2(acc[2 * j + 1]);
                redg_v4(&g_h[(size_t)gr0 * HID + 4 * j],
                        make_float4(u0.x, u0.y, u1.x, u1.y));
            }
        }
        if (gr1 < NN) {
#pragma unroll
            for (int j = 0; j < 4; j++) {
                float2 u0 = unpack2(acc[8 + 2 * j]);
                float2 u1 = unpack2(acc[8 + 2 * j + 1]);
                redg_v4(&g_h[(size_t)gr1 * HID + 4 * j],
                        make_float4(u0.x, u0.y, u1.x, u1.y));
            }
        }
    }
}

// ---------- K4: scatter layer 1 (norm_src applied per edge) ----------
__global__ void k_scatter1(const void* __restrict__ src, const void* __restrict__ dst,
                           int nE) {
    int e = blockIdx.x * blockDim.x + threadIdx.x;
    if (e >= nE) return;
    int is64 = g_is64;
    int s = eidx(src, e, is64), d = eidx(dst, e, is64);
    float f = g_norm_src[s];
    const float4* hp = (const float4*)(g_h + (size_t)s * HID);
    float* ap = g_agg1 + (size_t)d * HID;
#pragma unroll
    for (int qd = 0; qd < 4; qd++) {
        float4 v = hp[qd];
        v.x *= f; v.y *= f; v.z *= f; v.w *= f;
        redg_v4(ap + 4 * qd, v);
    }
}

// ---------- K5: h1 = relu(agg1*norm_dst + b1); h2 = (h1*norm_src) @ W2 ----------
__global__ void k_layer2(const float* __restrict__ b1, const float* __restrict__ W2) {
    int n = blockIdx.x * blockDim.x + threadIdx.x;
    if (n >= NN) return;
    float nd = g_norm_dst[n], ns = g_norm_src[n];
    float h1[HID];
    const float4* ap = (const float4*)(g_agg1 + (size_t)n * HID);
#pragma unroll
    for (int qd = 0; qd < 4; qd++) {
        float4 v = ap[qd];
        h1[4 * qd + 0] = fmaxf(fmaf(v.x, nd, __ldg(&b1[4 * qd + 0])), 0.f);
        h1[4 * qd + 1] = fmaxf(fmaf(v.y, nd, __ldg(&b1[4 * qd + 1])), 0.f);
        h1[4 * qd + 2] = fmaxf(fmaf(v.z, nd, __ldg(&b1[4 * qd + 2])), 0.f);
        h1[4 * qd + 3] = fmaxf(fmaf(v.w, nd, __ldg(&b1[4 * qd + 3])), 0.f);
    }
    float o[LAB];
#pragma unroll
    for (int j = 0; j < LAB; j++) o[j] = 0.f;
#pragma unroll
    for (int k = 0; k < HID; k++) {
        float hv = h1[k];
#pragma unroll
        for (int j = 0; j < LAB; j++) o[j] = fmaf(hv, __ldg(&W2[k * LAB + j]), o[j]);
    }
#pragma unroll
    for (int j = 0; j < LAB; j++) g_h2[n * 8 + j] = ns * o[j];
    g_h2[n * 8 + 7] = 0.f;
}

// ---------- K6: scatter layer 2 ----------
__global__ void k_scatter2(const void* __restrict__ src, const void* __restrict__ dst,
                           int nE) {
    int e = blockIdx.x * blockDim.x + threadIdx.x;
    if (e >= nE) return;
    int is64 = g_is64;
    int s = eidx(src, e, is64), d = eidx(dst, e, is64);
    const float4* hp = (const float4*)(g_h2 + (size_t)s * 8);
    float4 v0 = hp[0], v1 = hp[1];
    float* ap = g_agg2 + (size_t)d * 8;
    redg_v4(ap, v0);
    redg_v4(ap + 4, v1);
}

// ---------- K7: finalize ----------
__global__ void k_final(const float* __restrict__ b2, float* __restrict__ out) {
    int i = blockIdx.x * blockDim.x + threadIdx.x;
    if (i >= NN * LAB) return;
    int n = i / LAB, j = i - n * LAB;
    out[i] = fmaf(g_agg2[n * 8 + j], g_norm_dst[n], __ldg(&b2[j]));
}

extern "C" void kernel_launch(void* const* d_in, const int* in_sizes, int n_in,
                              void* d_out, int out_size) {
    const float* feat = (const float*)d_in[0];
    const void* src = d_in[1];
    const void* dst = d_in[2];
    const float* W1 = (const float*)d_in[3];
    const float* b1 = (const float*)d_in[4];
    const float* W2 = (const float*)d_in[5];
    const float* b2 = (const float*)d_in[6];
    int nE = in_sizes[1];
    float* out = (float*)d_out;

    int eb = (nE + 255) / 256;

    k_init<<<256, 256>>>((const int*)src);
    k_deg<<<eb, 256>>>(src, dst, nE);
    k_norm<<<(NN + 255) / 256, 256>>>();
    dim3 g1((NN + RPB - 1) / RPB, KSPLIT);     // 157 x 32 = 5024 blocks
    k_gemm1<<<g1, 256>>>(feat, W1);
    k_scatter1<<<eb, 256>>>(src, dst, nE);
    k_layer2<<<(NN + 255) / 256, 256>>>(b1, W2);
    k_scatter2<<<eb, 256>>>(src, dst, nE);
    k_final<<<(NN * LAB + 255) / 256, 256>>>(b2, out);
}

// round 8
// speedup vs baseline: 1.0258x; 1.0258x over previous
#include <cuda_runtime.h>

#define NN 10000
#define HID 16
#define LAB 7
#define KC 32             // k per chunk
#define RPB 64            // rows per block
#define PITCH4 9          // float4 pitch (odd -> conflict-free LDS.128)
#define NCHT 313          // ceil(10000/32)
#define KSPLIT 16
#define NUNITS (157 * KSPLIT)
#define DEPTH 4
#define PGRID 296         // 2 blocks per SM, single wave

__device__ int g_is64;
__device__ unsigned g_ctr;
__device__ __align__(16) float g_deg_src[NN];
__device__ __align__(16) float g_deg_dst[NN];
__device__ __align__(16) float g_norm_src[NN];
__device__ __align__(16) float g_norm_dst[NN];
__device__ __align__(16) float g_h[NN * HID];   // features @ W1 (unnormalized)
__device__ __align__(16) float g_agg1[NN * HID];
__device__ __align__(16) float g_h2[NN * 8];
__device__ __align__(16) float g_agg2[NN * 8];

// ---------- helpers ----------
__device__ __forceinline__ unsigned long long pack2(float x) {
    unsigned long long r;
    asm("mov.b64 %0, {%1, %1};" : "=l"(r) : "f"(x));
    return r;
}
__device__ __forceinline__ void fma2(unsigned long long& d, unsigned long long a,
                                     unsigned long long b) {
    asm("fma.rn.f32x2 %0, %1, %2, %0;" : "+l"(d) : "l"(a), "l"(b));
}
__device__ __forceinline__ float2 unpack2(unsigned long long v) {
    float2 u;
    asm("mov.b64 {%0, %1}, %2;" : "=f"(u.x), "=f"(u.y) : "l"(v));
    return u;
}
__device__ __forceinline__ void redg_v4(float* p, float4 v) {
    unsigned long long gp;
    asm("cvta.to.global.u64 %0, %1;" : "=l"(gp) : "l"(p));
    asm volatile("red.global.add.v4.f32 [%0], {%1, %2, %3, %4};"
                 ::"l"(gp), "f"(v.x), "f"(v.y), "f"(v.z), "f"(v.w) : "memory");
}
__device__ __forceinline__ void redg_f32(float* p, float v) {
    unsigned long long gp;
    asm("cvta.to.global.u64 %0, %1;" : "=l"(gp) : "l"(p));
    asm volatile("red.global.add.f32 [%0], %1;" ::"l"(gp), "f"(v) : "memory");
}
__device__ __forceinline__ void cp16(unsigned smem_dst, const void* gsrc, int sz) {
    asm volatile("cp.async.cg.shared.global [%0], [%1], 16, %2;"
                 ::"r"(smem_dst), "l"(gsrc), "r"(sz));
}
__device__ __forceinline__ int eidx(const void* p, int e, int is64) {
    int v = ((const int*)p)[is64 ? 2 * e : e];
    return min(max(v, 0), NN - 1);
}

// ---------- K0: detect dtype + zero scratch + reset counter ----------
__global__ void k_init(const int* __restrict__ src) {
    int i = blockIdx.x * blockDim.x + threadIdx.x;
    if (i == 0) {
        int all_odd_zero = 1;
        for (int t = 1; t < 256; t += 2)
            if (src[t] != 0) { all_odd_zero = 0; break; }
        g_is64 = all_odd_zero;
        g_ctr = 0u;
    }
    int stride = gridDim.x * blockDim.x;
    for (int t = i; t < NN; t += stride) { g_deg_src[t] = 0.f; g_deg_dst[t] = 0.f; }
    for (int t = i; t < NN * HID; t += stride) { g_h[t] = 0.f; g_agg1[t] = 0.f; }
    for (int t = i; t < NN * 8; t += stride) g_agg2[t] = 0.f;
}

// ---------- K1: degrees ----------
__global__ void k_deg(const void* __restrict__ src, const void* __restrict__ dst, int nE) {
    int e = blockIdx.x * blockDim.x + threadIdx.x;
    if (e >= nE) return;
    int is64 = g_is64;
    redg_f32(&g_deg_src[eidx(src, e, is64)], 1.f);
    redg_f32(&g_deg_dst[eidx(dst, e, is64)], 1.f);
}

// ---------- K2: norms ----------
__global__ void k_norm() {
    int n = blockIdx.x * blockDim.x + threadIdx.x;
    if (n >= NN) return;
    g_norm_src[n] = rsqrtf(fmaxf(g_deg_src[n], 1.f));
    g_norm_dst[n] = rsqrtf(fmaxf(g_deg_dst[n], 1.f));
}

// ---------- K3: persistent GEMM, work-stolen units ----------
// Unit = 64-row tile x 1/16 of K (19-20 chunks of KC=32). 296 blocks (2/SM,
// one wave) grab units from g_ctr. Per unit: depth-4 cp.async ring (R6
// schedule), cross-warp smem reduce, RED partials into g_h.
__global__ void __launch_bounds__(256, 2)
k_gemm1(const float* __restrict__ feat, const float* __restrict__ W1) {
    __shared__ __align__(16) float4 sF[DEPTH][RPB * PITCH4];   // 36864 B
    __shared__ __align__(16) float4 sW[DEPTH][KC * HID / 4];   // 8192 B
    __shared__ int s_unit;

    const int tid = threadIdx.x;
    const int w = tid >> 5;
    const int lane = tid & 31;
    const int fr = tid >> 3;          // staging row 0..31 (+32)
    const int fq = tid & 7;           // staging quad in row
    const float4* W14 = (const float4*)W1;

    for (;;) {
        if (tid == 0) s_unit = (int)atomicAdd(&g_ctr, 1u);
        __syncthreads();
        const int u = s_unit;
        if (u >= NUNITS) return;

        const int rowBase = (u >> 4) * RPB;
        const int ks = u & 15;
        const int ch0 = (ks * NCHT) / KSPLIT;
        const int nch = ((ks + 1) * NCHT) / KSPLIT - ch0;

        auto issue = [&](int c) {
            if (c < nch) {
                const int b = c & (DEPTH - 1);
                const int c0 = (ch0 + c) * KC;
                const int gc = c0 + 4 * fq;
                const int okc = (gc < NN);
#pragma unroll
                for (int i = 0; i < 2; i++) {
                    int r = fr + 32 * i;
                    int gr = rowBase + r;
                    int ok = (okc && gr < NN);
                    const float* s = feat + (size_t)min(gr, NN - 1) * NN + min(gc, NN - 4);
                    cp16((unsigned)__cvta_generic_to_shared(&sF[b][r * PITCH4 + fq]), s,
                         ok ? 16 : 0);
                }
                if (tid < KC * HID / 4) {
                    int gq = c0 * 4 + tid;
                    int ok = (gq < NN * 4);
                    cp16((unsigned)__cvta_generic_to_shared(&sW[b][tid]),
                         W14 + min(gq, NN * 4 - 1), ok ? 16 : 0);
                }
            }
            asm volatile("cp.async.commit_group;" ::: "memory");
        };

        unsigned long long a0[8], a1[8];
#pragma unroll
        for (int i = 0; i < 8; i++) { a0[i] = 0ull; a1[i] = 0ull; }

        issue(0); issue(1); issue(2);

        for (int c = 0; c < nch; c++) {
            const int b = c & (DEPTH - 1);
            asm volatile("cp.async.wait_group %0;" ::"n"(DEPTH - 2) : "memory");
            __syncthreads();

            const float* wB = (const float*)sW[b];
            float4 f0 = sF[b][lane * PITCH4 + w];
            float4 f1 = sF[b][(lane + 32) * PITCH4 + w];
            const float fa0[4] = {f0.x, f0.y, f0.z, f0.w};
            const float fa1[4] = {f1.x, f1.y, f1.z, f1.w};
#pragma unroll
            for (int m = 0; m < 4; m++) {
                const ulonglong2* wr = (const ulonglong2*)(wB + (w * 4 + m) * HID);
                ulonglong2 q0 = wr[0], q1 = wr[1], q2 = wr[2], q3 = wr[3];
                unsigned long long p0 = pack2(fa0[m]);
                unsigned long long p1 = pack2(fa1[m]);
                fma2(a0[0], q0.x, p0); fma2(a0[1], q0.y, p0);
                fma2(a0[2], q1.x, p0); fma2(a0[3], q1.y, p0);
                fma2(a0[4], q2.x, p0); fma2(a0[5], q2.y, p0);
                fma2(a0[6], q3.x, p0); fma2(a0[7], q3.y, p0);
                fma2(a1[0], q0.x, p1); fma2(a1[1], q0.y, p1);
                fma2(a1[2], q1.x, p1); fma2(a1[3], q1.y, p1);
                fma2(a1[4], q2.x, p1); fma2(a1[5], q2.y, p1);
                fma2(a1[6], q3.x, p1); fma2(a1[7], q3.y, p1);
            }
            issue(c + 3);
        }
        asm volatile("cp.async.wait_group 0;" ::: "memory");
        __syncthreads();

        // cross-warp reduce; reuse sF as scratch (needs 8192 floats)
        float* red = (float*)sF;
#pragma unroll
        for (int i = 0; i < 8; i++) {
            float2 u0 = unpack2(a0[i]);
            float2 u1 = unpack2(a1[i]);
            red[((2 * i) * 8 + w) * RPB + lane] = u0.x;
            red[((2 * i + 1) * 8 + w) * RPB + lane] = u0.y;
            red[((2 * i) * 8 + w) * RPB + lane + 32] = u1.x;
            red[((2 * i + 1) * 8 + w) * RPB + lane + 32] = u1.y;
        }
        __syncthreads();
        {
            const int r = tid >> 2;
            const int qc = tid & 3;
            const int gr = rowBase + r;
            if (gr < NN) {
                float s[4] = {0.f, 0.f, 0.f, 0.f};
#pragma unroll
                for (int ww = 0; ww < 8; ww++)
#pragma unroll
                    for (int m = 0; m < 4; m++)
                        s[m] += red[((qc * 4 + m) * 8 + ww) * RPB + r];
                redg_v4(&g_h[(size_t)gr * HID + qc * 4],
                        make_float4(s[0], s[1], s[2], s[3]));
            }
        }
        __syncthreads();   // protect sF before next unit's issues
    }
}

// ---------- K4: scatter layer 1 (norm_src applied per edge) ----------
__global__ void k_scatter1(const void* __restrict__ src, const void* __restrict__ dst,
                           int nE) {
    int e = blockIdx.x * blockDim.x + threadIdx.x;
    if (e >= nE) return;
    int is64 = g_is64;
    int s = eidx(src, e, is64), d = eidx(dst, e, is64);
    float f = g_norm_src[s];
    const float4* hp = (const float4*)(g_h + (size_t)s * HID);
    float* ap = g_agg1 + (size_t)d * HID;
#pragma unroll
    for (int q = 0; q < 4; q++) {
        float4 v = hp[q];
        v.x *= f; v.y *= f; v.z *= f; v.w *= f;
        redg_v4(ap + 4 * q, v);
    }
}

// ---------- K5: h1 = relu(agg1*norm_dst + b1); h2 = (h1*norm_src) @ W2 ----------
__global__ void k_layer2(const float* __restrict__ b1, const float* __restrict__ W2) {
    int n = blockIdx.x * blockDim.x + threadIdx.x;
    if (n >= NN) return;
    float nd = g_norm_dst[n], ns = g_norm_src[n];
    float h1[HID];
    const float4* ap = (const float4*)(g_agg1 + (size_t)n * HID);
#pragma unroll
    for (int q = 0; q < 4; q++) {
        float4 v = ap[q];
        h1[4 * q + 0] = fmaxf(fmaf(v.x, nd, __ldg(&b1[4 * q + 0])), 0.f);
        h1[4 * q + 1] = fmaxf(fmaf(v.y, nd, __ldg(&b1[4 * q + 1])), 0.f);
        h1[4 * q + 2] = fmaxf(fmaf(v.z, nd, __ldg(&b1[4 * q + 2])), 0.f);
        h1[4 * q + 3] = fmaxf(fmaf(v.w, nd, __ldg(&b1[4 * q + 3])), 0.f);
    }
    float o[LAB];
#pragma unroll
    for (int j = 0; j < LAB; j++) o[j] = 0.f;
#pragma unroll
    for (int k = 0; k < HID; k++) {
        float hv = h1[k];
#pragma unroll
        for (int j = 0; j < LAB; j++) o[j] = fmaf(hv, __ldg(&W2[k * LAB + j]), o[j]);
    }
#pragma unroll
    for (int j = 0; j < LAB; j++) g_h2[n * 8 + j] = ns * o[j];
    g_h2[n * 8 + 7] = 0.f;
}

// ---------- K6: scatter layer 2 ----------
__global__ void k_scatter2(const void* __restrict__ src, const void* __restrict__ dst,
                           int nE) {
    int e = blockIdx.x * blockDim.x + threadIdx.x;
    if (e >= nE) return;
    int is64 = g_is64;
    int s = eidx(src, e, is64), d = eidx(dst, e, is64);
    const float4* hp = (const float4*)(g_h2 + (size_t)s * 8);
    float4 v0 = hp[0], v1 = hp[1];
    float* ap = g_agg2 + (size_t)d * 8;
    redg_v4(ap, v0);
    redg_v4(ap + 4, v1);
}

// ---------- K7: finalize ----------
__global__ void k_final(const float* __restrict__ b2, float* __restrict__ out) {
    int i = blockIdx.x * blockDim.x + threadIdx.x;
    if (i >= NN * LAB) return;
    int n = i / LAB, j = i - n * LAB;
    out[i] = fmaf(g_agg2[n * 8 + j], g_norm_dst[n], __ldg(&b2[j]));
}

extern "C" void kernel_launch(void* const* d_in, const int* in_sizes, int n_in,
                              void* d_out, int out_size) {
    const float* feat = (const float*)d_in[0];
    const void* src = d_in[1];
    const void* dst = d_in[2];
    const float* W1 = (const float*)d_in[3];
    const float* b1 = (const float*)d_in[4];
    const float* W2 = (const float*)d_in[5];
    const float* b2 = (const float*)d_in[6];
    int nE = in_sizes[1];
    float* out = (float*)d_out;

    int eb = (nE + 255) / 256;

    k_init<<<256, 256>>>((const int*)src);
    k_deg<<<eb, 256>>>(src, dst, nE);
    k_norm<<<(NN + 255) / 256, 256>>>();
    k_gemm1<<<PGRID, 256>>>(feat, W1);
    k_scatter1<<<eb, 256>>>(src, dst, nE);
    k_layer2<<<(NN + 255) / 256, 256>>>(b1, W2);
    k_scatter2<<<eb, 256>>>(src, dst, nE);
    k_final<<<(NN * LAB + 255) / 256, 256>>>(b2, out);
}

// round 9
// speedup vs baseline: 1.4739x; 1.4368x over previous
#include <cuda_runtime.h>
#include <cstdint>

#define NN 10000
#define HID 16
#define LAB 7
#define KC 32             // k per chunk
#define RPB 64            // rows per block
#define FP 36             // feat smem pitch (floats): ldmatrix conflict-free
#define WP 24             // W smem pitch (floats): b-frag conflict-free
#define NCHT 313          // ceil(10000/32)
#define KSPLIT 16
#define NUNITS (157 * KSPLIT)
#define PGRID 592         // 4 blocks/SM, single persistent wave

__device__ int g_is64;
__device__ unsigned g_ctr;
__device__ __align__(16) float g_deg_src[NN];
__device__ __align__(16) float g_deg_dst[NN];
__device__ __align__(16) float g_norm_src[NN];
__device__ __align__(16) float g_norm_dst[NN];
__device__ __align__(16) float g_h[NN * HID];   // features @ W1 (unnormalized)
__device__ __align__(16) float g_agg1[NN * HID];
__device__ __align__(16) float g_h2[NN * 8];
__device__ __align__(16) float g_agg2[NN * 8];

// ---------- helpers ----------
__device__ __forceinline__ void redg_v4(float* p, float4 v) {
    unsigned long long gp;
    asm("cvta.to.global.u64 %0, %1;" : "=l"(gp) : "l"(p));
    asm volatile("red.global.add.v4.f32 [%0], {%1, %2, %3, %4};"
                 ::"l"(gp), "f"(v.x), "f"(v.y), "f"(v.z), "f"(v.w) : "memory");
}
__device__ __forceinline__ void redg_v2(float* p, float a, float b) {
    unsigned long long gp;
    asm("cvta.to.global.u64 %0, %1;" : "=l"(gp) : "l"(p));
    asm volatile("red.global.add.v2.f32 [%0], {%1, %2};"
                 ::"l"(gp), "f"(a), "f"(b) : "memory");
}
__device__ __forceinline__ void redg_f32(float* p, float v) {
    unsigned long long gp;
    asm("cvta.to.global.u64 %0, %1;" : "=l"(gp) : "l"(p));
    asm volatile("red.global.add.f32 [%0], %1;" ::"l"(gp), "f"(v) : "memory");
}
__device__ __forceinline__ void cp16(unsigned smem_dst, const void* gsrc, int sz) {
    asm volatile("cp.async.cg.shared.global [%0], [%1], 16, %2;"
                 ::"r"(smem_dst), "l"(gsrc), "r"(sz));
}
__device__ __forceinline__ unsigned tf32(float f) {
    unsigned r;
    asm("cvt.rna.tf32.f32 %0, %1;" : "=r"(r) : "f"(f));
    return r;
}
__device__ __forceinline__ void ldm4(unsigned* a, unsigned addr) {
    asm volatile("ldmatrix.sync.aligned.m8n8.x4.shared.b16 {%0,%1,%2,%3}, [%4];"
                 : "=r"(a[0]), "=r"(a[1]), "=r"(a[2]), "=r"(a[3]) : "r"(addr));
}
__device__ __forceinline__ void mma8(float* d, const unsigned* a, unsigned b0,
                                     unsigned b1) {
    asm volatile(
        "mma.sync.aligned.m16n8k8.row.col.f32.tf32.tf32.f32 "
        "{%0,%1,%2,%3}, {%4,%5,%6,%7}, {%8,%9}, {%0,%1,%2,%3};"
        : "+f"(d[0]), "+f"(d[1]), "+f"(d[2]), "+f"(d[3])
        : "r"(a[0]), "r"(a[1]), "r"(a[2]), "r"(a[3]), "r"(b0), "r"(b1));
}
__device__ __forceinline__ int eidx(const void* p, int e, int is64) {
    int v = ((const int*)p)[is64 ? 2 * e : e];
    return min(max(v, 0), NN - 1);
}

// ---------- K0: detect dtype + zero scratch + reset counter ----------
__global__ void k_init(const int* __restrict__ src) {
    int i = blockIdx.x * blockDim.x + threadIdx.x;
    if (i == 0) {
        int all_odd_zero = 1;
        for (int t = 1; t < 256; t += 2)
            if (src[t] != 0) { all_odd_zero = 0; break; }
        g_is64 = all_odd_zero;
        g_ctr = 0u;
    }
    int stride = gridDim.x * blockDim.x;
    for (int t = i; t < NN; t += stride) { g_deg_src[t] = 0.f; g_deg_dst[t] = 0.f; }
    for (int t = i; t < NN * HID; t += stride) { g_h[t] = 0.f; g_agg1[t] = 0.f; }
    for (int t = i; t < NN * 8; t += stride) g_agg2[t] = 0.f;
}

// ---------- K1: degrees ----------
__global__ void k_deg(const void* __restrict__ src, const void* __restrict__ dst, int nE) {
    int e = blockIdx.x * blockDim.x + threadIdx.x;
    if (e >= nE) return;
    int is64 = g_is64;
    redg_f32(&g_deg_src[eidx(src, e, is64)], 1.f);
    redg_f32(&g_deg_dst[eidx(dst, e, is64)], 1.f);
}

// ---------- K2: norms ----------
__global__ void k_norm() {
    int n = blockIdx.x * blockDim.x + threadIdx.x;
    if (n >= NN) return;
    g_norm_src[n] = rsqrtf(fmaxf(g_deg_src[n], 1.f));
    g_norm_dst[n] = rsqrtf(fmaxf(g_deg_dst[n], 1.f));
}

// ---------- K3: persistent tf32 tensor-core GEMM ----------
// Unit = 64-row tile x 1/16 of K (19-20 chunks of KC=32). 592 blocks, 4/SM.
// Per chunk: warp w = m-tile (w&3) x k-half (w>>2); 2 ldmatrix.x4 (A),
// 8 LDS.32 (B, conflict-free pitch 24), 16 cvt.rna.tf32, 4 mma.m16n8k8.
// Epilogue: warp pairs (w, w+4) reduce via smem, red.v2 partials to g_h.
__global__ void __launch_bounds__(256, 4)
k_gemm1(const float* __restrict__ feat, const float* __restrict__ W1) {
    __shared__ __align__(16) float sF[3][RPB * FP];     // 27648 B
    __shared__ __align__(16) float sW[3][KC * WP];      // 9216 B
    __shared__ __align__(16) float sD[4][256];          // 4096 B
    __shared__ int s_unit;

    const int tid = threadIdx.x;
    const int w = tid >> 5;
    const int lane = tid & 31;
    const int mt = w & 3;
    const int kh = w >> 2;
    const int g_ = lane >> 2;
    const int t_ = lane & 3;
    // ldmatrix per-lane row/col within the warp's m16 x k8 A tile
    const int lrow = mt * 16 + ((lane >> 3) & 1) * 8 + (lane & 7);
    const int lcol = ((lane >> 4) & 1) * 4 + kh * 16;

    for (;;) {
        if (tid == 0) s_unit = (int)atomicAdd(&g_ctr, 1u);
        __syncthreads();
        const int u = s_unit;
        if (u >= NUNITS) return;

        const int rowBase = (u >> 4) * RPB;
        const int ks = u & 15;
        const int ch0 = (ks * NCHT) / KSPLIT;
        const int nch = ((ks + 1) * NCHT) / KSPLIT - ch0;

        auto issue = [&](int c) {
            if (c < nch) {
                const int b = c % 3;
                const int c0k = (ch0 + c) * KC;
#pragma unroll
                for (int i = 0; i < 2; i++) {
                    int uu = tid + 256 * i;
                    int row = uu >> 3, quad = uu & 7;
                    int gr = rowBase + row, gc = c0k + quad * 4;
                    int ok = (gr < NN && gc < NN);
                    cp16((unsigned)__cvta_generic_to_shared(&sF[b][row * FP + quad * 4]),
                         feat + (size_t)min(gr, NN - 1) * NN + min(gc, NN - 4),
                         ok ? 16 : 0);
                }
                if (tid < 128) {
                    int row = tid >> 2, quad = tid & 3;
                    int gk = c0k + row;
                    cp16((unsigned)__cvta_generic_to_shared(&sW[b][row * WP + quad * 4]),
                         W1 + (size_t)min(gk, NN - 1) * HID + quad * 4,
                         (gk < NN) ? 16 : 0);
                }
            }
            asm volatile("cp.async.commit_group;" ::: "memory");
        };

        float d[2][4];
#pragma unroll
        for (int nt = 0; nt < 2; nt++)
#pragma unroll
            for (int i = 0; i < 4; i++) d[nt][i] = 0.f;

        issue(0); issue(1);

        for (int c = 0; c < nch; c++) {
            const int b = c % 3;
            asm volatile("cp.async.wait_group 1;" ::: "memory");
            __syncthreads();

            const float* fb = sF[b];
            const float* wb = sW[b];
#pragma unroll
            for (int kt = 0; kt < 2; kt++) {
                unsigned a[4];
                ldm4(a, (unsigned)__cvta_generic_to_shared(
                            &fb[lrow * FP + lcol + kt * 8]));
#pragma unroll
                for (int i = 0; i < 4; i++) a[i] = tf32(__uint_as_float(a[i]));
                const int bk = kh * 16 + kt * 8 + t_;
#pragma unroll
                for (int nt = 0; nt < 2; nt++) {
                    unsigned b0 = tf32(wb[bk * WP + nt * 8 + g_]);
                    unsigned b1 = tf32(wb[(bk + 4) * WP + nt * 8 + g_]);
                    mma8(d[nt], a, b0, b1);
                }
            }
            issue(c + 2);
        }

        // pairwise cross-warp reduce: warps 4-7 stash, warps 0-3 combine + RED
        if (w >= 4) {
#pragma unroll
            for (int nt = 0; nt < 2; nt++) {
                sD[mt][g_ * 16 + nt * 8 + 2 * t_] = d[nt][0];
                sD[mt][g_ * 16 + nt * 8 + 2 * t_ + 1] = d[nt][1];
                sD[mt][(g_ + 8) * 16 + nt * 8 + 2 * t_] = d[nt][2];
                sD[mt][(g_ + 8) * 16 + nt * 8 + 2 * t_ + 1] = d[nt][3];
            }
        }
        __syncthreads();
        if (w < 4) {
            const int gr0 = rowBase + mt * 16 + g_;
            const int gr1 = gr0 + 8;
#pragma unroll
            for (int nt = 0; nt < 2; nt++) {
                float v0 = d[nt][0] + sD[mt][g_ * 16 + nt * 8 + 2 * t_];
                float v1 = d[nt][1] + sD[mt][g_ * 16 + nt * 8 + 2 * t_ + 1];
                float v2 = d[nt][2] + sD[mt][(g_ + 8) * 16 + nt * 8 + 2 * t_];
                float v3 = d[nt][3] + sD[mt][(g_ + 8) * 16 + nt * 8 + 2 * t_ + 1];
                if (gr0 < NN) redg_v2(&g_h[(size_t)gr0 * HID + nt * 8 + 2 * t_], v0, v1);
                if (gr1 < NN) redg_v2(&g_h[(size_t)gr1 * HID + nt * 8 + 2 * t_], v2, v3);
            }
        }
    }
}

// ---------- K4: scatter layer 1 (norm_src applied per edge) ----------
__global__ void k_scatter1(const void* __restrict__ src, const void* __restrict__ dst,
                           int nE) {
    int e = blockIdx.x * blockDim.x + threadIdx.x;
    if (e >= nE) return;
    int is64 = g_is64;
    int s = eidx(src, e, is64), d = eidx(dst, e, is64);
    float f = g_norm_src[s];
    const float4* hp = (const float4*)(g_h + (size_t)s * HID);
    float* ap = g_agg1 + (size_t)d * HID;
#pragma unroll
    for (int q = 0; q < 4; q++) {
        float4 v = hp[q];
        v.x *= f; v.y *= f; v.z *= f; v.w *= f;
        redg_v4(ap + 4 * q, v);
    }
}

// ---------- K5: h1 = relu(agg1*norm_dst + b1); h2 = (h1*norm_src) @ W2 ----------
__global__ void k_layer2(const float* __restrict__ b1, const float* __restrict__ W2) {
    int n = blockIdx.x * blockDim.x + threadIdx.x;
    if (n >= NN) return;
    float nd = g_norm_dst[n], ns = g_norm_src[n];
    float h1[HID];
    const float4* ap = (const float4*)(g_agg1 + (size_t)n * HID);
#pragma unroll
    for (int q = 0; q < 4; q++) {
        float4 v = ap[q];
        h1[4 * q + 0] = fmaxf(fmaf(v.x, nd, __ldg(&b1[4 * q + 0])), 0.f);
        h1[4 * q + 1] = fmaxf(fmaf(v.y, nd, __ldg(&b1[4 * q + 1])), 0.f);
        h1[4 * q + 2] = fmaxf(fmaf(v.z, nd, __ldg(&b1[4 * q + 2])), 0.f);
        h1[4 * q + 3] = fmaxf(fmaf(v.w, nd, __ldg(&b1[4 * q + 3])), 0.f);
    }
    float o[LAB];
#pragma unroll
    for (int j = 0; j < LAB; j++) o[j] = 0.f;
#pragma unroll
    for (int k = 0; k < HID; k++) {
        float hv = h1[k];
#pragma unroll
        for (int j = 0; j < LAB; j++) o[j] = fmaf(hv, __ldg(&W2[k * LAB + j]), o[j]);
    }
#pragma unroll
    for (int j = 0; j < LAB; j++) g_h2[n * 8 + j] = ns * o[j];
    g_h2[n * 8 + 7] = 0.f;
}

// ---------- K6: scatter layer 2 ----------
__global__ void k_scatter2(const void* __restrict__ src, const void* __restrict__ dst,
                           int nE) {
    int e = blockIdx.x * blockDim.x + threadIdx.x;
    if (e >= nE) return;
    int is64 = g_is64;
    int s = eidx(src, e, is64), d = eidx(dst, e, is64);
    const float4* hp = (const float4*)(g_h2 + (size_t)s * 8);
    float4 v0 = hp[0], v1 = hp[1];
    float* ap = g_agg2 + (size_t)d * 8;
    redg_v4(ap, v0);
    redg_v4(ap + 4, v1);
}

// ---------- K7: finalize ----------
__global__ void k_final(const float* __restrict__ b2, float* __restrict__ out) {
    int i = blockIdx.x * blockDim.x + threadIdx.x;
    if (i >= NN * LAB) return;
    int n = i / LAB, j = i - n * LAB;
    out[i] = fmaf(g_agg2[n * 8 + j], g_norm_dst[n], __ldg(&b2[j]));
}

extern "C" void kernel_launch(void* const* d_in, const int* in_sizes, int n_in,
                              void* d_out, int out_size) {
    const float* feat = (const float*)d_in[0];
    const void* src = d_in[1];
    const void* dst = d_in[2];
    const float* W1 = (const float*)d_in[3];
    const float* b1 = (const float*)d_in[4];
    const float* W2 = (const float*)d_in[5];
    const float* b2 = (const float*)d_in[6];
    int nE = in_sizes[1];
    float* out = (float*)d_out;

    int eb = (nE + 255) / 256;

    k_init<<<256, 256>>>((const int*)src);
    k_deg<<<eb, 256>>>(src, dst, nE);
    k_norm<<<(NN + 255) / 256, 256>>>();
    k_gemm1<<<PGRID, 256>>>(feat, W1);
    k_scatter1<<<eb, 256>>>(src, dst, nE);
    k_layer2<<<(NN + 255) / 256, 256>>>(b1, W2);
    k_scatter2<<<eb, 256>>>(src, dst, nE);
    k_final<<<(NN * LAB + 255) / 256, 256>>>(b2, out);
}